// round 4
// baseline (speedup 1.0000x reference)
#include <cuda_runtime.h>
#include <cuda_bf16.h>
#include <cstdint>

#define NUM_CLASSES 1000
#define FEAT_DIM    512
#define BATCH       32768
// ALPHA = 0.5, (1-ALPHA) = 0.5

// Scratch (device globals, allocation-free). Zero at module load; every
// kernel_launch restores them to zero => deterministic across graph replays.
__device__ __align__(16) float g_sums[NUM_CLASSES * FEAT_DIM];
__device__ float g_counts[NUM_CLASSES];
__device__ float g_loss;
__device__ unsigned int g_done;

// ---------------------------------------------------------------------------
// Main pass: one warp per batch row. Reads ONLY features + labels.
// Accumulates sum(f*f) into g_loss and scatters the row into g_sums[label]
// via no-return vectorized global reduction (REDG v4).
// Loss is reconstructed in finalize via the expansion:
//   sum ||f - c[lab]||^2 = sum f^2 - 2 sum_c <s_c, c_c> + sum_c cnt_c ||c_c||^2
// ---------------------------------------------------------------------------
__global__ void __launch_bounds__(256) center_main_kernel(
    const float* __restrict__ features,
    const int* __restrict__ labels)
{
    const int tid  = blockIdx.x * blockDim.x + threadIdx.x;
    const int row  = tid >> 5;           // one warp per row, grid sized exactly
    const int lane = threadIdx.x & 31;

    float acc = 0.0f;

    if (row < BATCH) {
        const int lab = labels[row];
        const float4* __restrict__ f =
            reinterpret_cast<const float4*>(features + (size_t)row * FEAT_DIM);
        float* __restrict__ s = g_sums + (size_t)lab * FEAT_DIM;

        #pragma unroll
        for (int i = 0; i < 4; i++) {
            const int idx = lane + i * 32;   // float4 index within row (0..127)
            float4 fv = f[idx];
            acc += fv.x * fv.x + fv.y * fv.y + fv.z * fv.z + fv.w * fv.w;
            asm volatile("red.global.add.v4.f32 [%0], {%1, %2, %3, %4};"
                         :: "l"(s + idx * 4),
                            "f"(fv.x), "f"(fv.y), "f"(fv.z), "f"(fv.w)
                         : "memory");
        }
        if (lane == 0) atomicAdd(&g_counts[lab], 1.0f);
    }

    // ---- block-reduce sum(f^2) -> one atomic per block ----
    #pragma unroll
    for (int off = 16; off > 0; off >>= 1)
        acc += __shfl_xor_sync(0xffffffffu, acc, off);

    __shared__ float warp_sums[8];
    const int wid = threadIdx.x >> 5;
    if (lane == 0) warp_sums[wid] = acc;
    __syncthreads();
    if (threadIdx.x == 0) {
        float bs = 0.0f;
        #pragma unroll
        for (int w = 0; w < 8; w++) bs += warp_sums[w];
        atomicAdd(&g_loss, bs);
    }
}

// ---------------------------------------------------------------------------
// Finalize: one block per class (1000 blocks x 128 threads, 1 float4/thread).
//  - center update:  out = cnt>0 ? 0.5*c + 0.5*s/cnt : c
//  - loss terms:     cnt*c^2 - 2*c*s  (block-reduced, atomicAdd into g_loss)
//  - restores g_sums / g_counts to zero for the next call
//  - last block writes out[0] and resets g_loss / g_done
// ---------------------------------------------------------------------------
__global__ void __launch_bounds__(128) finalize_kernel(
    const float* __restrict__ centers,
    float* __restrict__ out)
{
    const int c = blockIdx.x;
    const int t = threadIdx.x;                 // 0..127 -> one float4 of the row
    const int lane = t & 31;
    const int wid  = t >> 5;

    const float cnt = g_counts[c];

    float4* __restrict__ srow =
        reinterpret_cast<float4*>(g_sums + (size_t)c * FEAT_DIM);
    const float4* __restrict__ crow =
        reinterpret_cast<const float4*>(centers + (size_t)c * FEAT_DIM);

    float4 sv = srow[t];
    float4 cv = crow[t];

    // loss partial: cnt*||c||^2 - 2*<c,s>   (zero automatically when cnt==0)
    float lp = cnt * (cv.x * cv.x + cv.y * cv.y + cv.z * cv.z + cv.w * cv.w)
             - 2.0f * (cv.x * sv.x + cv.y * sv.y + cv.z * sv.z + cv.w * sv.w);

    // center update (ALPHA = 0.5)
    float ox, oy, oz, ow;
    if (cnt > 0.0f) {
        const float inv = 0.5f / cnt;
        ox = 0.5f * cv.x + sv.x * inv;
        oy = 0.5f * cv.y + sv.y * inv;
        oz = 0.5f * cv.z + sv.z * inv;
        ow = 0.5f * cv.w + sv.w * inv;
    } else {
        ox = cv.x; oy = cv.y; oz = cv.z; ow = cv.w;
    }
    // out is offset by 1 (loss scalar at out[0]) -> 4B alignment, scalar stores
    float* o = out + 1 + (size_t)c * FEAT_DIM + t * 4;
    o[0] = ox; o[1] = oy; o[2] = oz; o[3] = ow;

    // restore scratch to zero for next launch
    srow[t] = make_float4(0.0f, 0.0f, 0.0f, 0.0f);

    // ---- block-reduce loss partial ----
    #pragma unroll
    for (int off = 16; off > 0; off >>= 1)
        lp += __shfl_xor_sync(0xffffffffu, lp, off);

    __shared__ float warp_sums[4];
    if (lane == 0) warp_sums[wid] = lp;
    __syncthreads();

    if (t == 0) {
        float bs = warp_sums[0] + warp_sums[1] + warp_sums[2] + warp_sums[3];
        atomicAdd(&g_loss, bs);
        g_counts[c] = 0.0f;
        __threadfence();
        unsigned int prev = atomicAdd(&g_done, 1u);
        if (prev == (unsigned int)(gridDim.x - 1)) {
            // all blocks' g_loss contributions are visible (fenced before done++)
            float lv = atomicAdd(&g_loss, 0.0f);   // L2-coherent read
            out[0] = 0.5f * lv / (float)BATCH;
            atomicExch(&g_loss, 0.0f);
            atomicExch(&g_done, 0u);
        }
    }
}

extern "C" void kernel_launch(void* const* d_in, const int* in_sizes, int n_in,
                              void* d_out, int out_size)
{
    const float* features = (const float*)d_in[0];
    const int*   labels   = (const int*)d_in[1];
    const float* centers  = (const float*)d_in[2];
    float*       out      = (float*)d_out;

    (void)in_sizes; (void)n_in; (void)out_size;

    // 1) fused pass: sum(f^2) + scatter sums/counts  (one warp per row)
    center_main_kernel<<<BATCH / 8, 256>>>(features, labels);
    // 2) finalize: center update + loss assembly + scratch re-zero
    finalize_kernel<<<NUM_CLASSES, 128>>>(centers, out);
}

// round 5
// speedup vs baseline: 1.0976x; 1.0976x over previous
#include <cuda_runtime.h>
#include <cuda_bf16.h>
#include <cstdint>

#define NUM_CLASSES 1000
#define FEAT_DIM    512
#define BATCH       32768
// ALPHA = 0.5, (1-ALPHA) = 0.5

// Scratch (device globals, allocation-free). Zero at module load; every
// kernel_launch restores them to zero => deterministic across graph replays.
__device__ __align__(16) float g_sums[NUM_CLASSES * FEAT_DIM];
__device__ float g_counts[NUM_CLASSES];
__device__ float g_loss;

// ---------------------------------------------------------------------------
// Main pass: one warp per TWO batch rows. Reads ONLY features + labels.
// Accumulates sum(f*f) toward the loss and scatters rows into g_sums[label]
// via no-return vectorized global reduction (REDG v4).
// Loss expansion (assembled in finalize):
//   sum ||f - c[lab]||^2 = sum f^2 - 2 sum_c <s_c, c_c> + sum_c cnt_c ||c_c||^2
// ---------------------------------------------------------------------------
__global__ void __launch_bounds__(256) center_main_kernel(
    const float* __restrict__ features,
    const int* __restrict__ labels)
{
    const int tid  = blockIdx.x * blockDim.x + threadIdx.x;
    const int warp = tid >> 5;
    const int lane = threadIdx.x & 31;
    const int row0 = warp * 2;              // grid sized exactly: BATCH/2 warps

    const int lab0 = labels[row0];
    const int lab1 = labels[row0 + 1];

    const float4* __restrict__ f0 =
        reinterpret_cast<const float4*>(features + (size_t)row0 * FEAT_DIM);
    const float4* __restrict__ f1 = f0 + (FEAT_DIM / 4);
    float* __restrict__ s0 = g_sums + (size_t)lab0 * FEAT_DIM;
    float* __restrict__ s1 = g_sums + (size_t)lab1 * FEAT_DIM;

    // hoist all 8 loads (MLP 8), then compute + scatter
    float4 a[4], b[4];
    #pragma unroll
    for (int i = 0; i < 4; i++) a[i] = f0[lane + i * 32];
    #pragma unroll
    for (int i = 0; i < 4; i++) b[i] = f1[lane + i * 32];

    float acc = 0.0f;
    #pragma unroll
    for (int i = 0; i < 4; i++) {
        const int idx = lane + i * 32;
        acc += a[i].x * a[i].x + a[i].y * a[i].y + a[i].z * a[i].z + a[i].w * a[i].w;
        asm volatile("red.global.add.v4.f32 [%0], {%1, %2, %3, %4};"
                     :: "l"(s0 + idx * 4),
                        "f"(a[i].x), "f"(a[i].y), "f"(a[i].z), "f"(a[i].w)
                     : "memory");
    }
    #pragma unroll
    for (int i = 0; i < 4; i++) {
        const int idx = lane + i * 32;
        acc += b[i].x * b[i].x + b[i].y * b[i].y + b[i].z * b[i].z + b[i].w * b[i].w;
        asm volatile("red.global.add.v4.f32 [%0], {%1, %2, %3, %4};"
                     :: "l"(s1 + idx * 4),
                        "f"(b[i].x), "f"(b[i].y), "f"(b[i].z), "f"(b[i].w)
                     : "memory");
    }
    if (lane == 0) {
        atomicAdd(&g_counts[lab0], 1.0f);
        atomicAdd(&g_counts[lab1], 1.0f);
    }

    // ---- block-reduce sum(f^2) -> one atomic per block ----
    #pragma unroll
    for (int off = 16; off > 0; off >>= 1)
        acc += __shfl_xor_sync(0xffffffffu, acc, off);

    __shared__ float warp_sums[8];
    const int wid = threadIdx.x >> 5;
    if (lane == 0) warp_sums[wid] = acc;
    __syncthreads();
    if (threadIdx.x == 0) {
        float bs = 0.0f;
        #pragma unroll
        for (int w = 0; w < 8; w++) bs += warp_sums[w];
        atomicAdd(&g_loss, bs);
    }
}

// ---------------------------------------------------------------------------
// Finalize: flat — 500 blocks x 256 threads = exactly 128000 threads,
// one float4 of the [1000 x 512] center matrix each. No fences, no done
// counter; loss scalar handled by the tail kernel.
//  - center update:  out = cnt>0 ? 0.5*c + 0.5*s/cnt : c
//  - loss terms:     cnt*c^2 - 2*c*s   (block-reduced -> one atomic/block)
//  - zeroes its own g_sums element for the next call
// ---------------------------------------------------------------------------
__global__ void __launch_bounds__(256) finalize_kernel(
    const float* __restrict__ centers,
    float* __restrict__ out)
{
    const int i = blockIdx.x * blockDim.x + threadIdx.x;   // float4 index
    const int c = i >> 7;                                   // 128 float4s/row
    const int lane = threadIdx.x & 31;
    const int wid  = threadIdx.x >> 5;

    const float cnt = g_counts[c];

    float4* __restrict__ sp = reinterpret_cast<float4*>(g_sums) + i;
    float4 sv = *sp;
    float4 cv = reinterpret_cast<const float4*>(centers)[i];

    // loss partial: cnt*||c||^2 - 2*<c,s>  (zero when cnt==0 since s==0)
    float lp = cnt * (cv.x * cv.x + cv.y * cv.y + cv.z * cv.z + cv.w * cv.w)
             - 2.0f * (cv.x * sv.x + cv.y * sv.y + cv.z * sv.z + cv.w * sv.w);

    float ox, oy, oz, ow;
    if (cnt > 0.0f) {
        const float inv = 0.5f / cnt;
        ox = 0.5f * cv.x + sv.x * inv;
        oy = 0.5f * cv.y + sv.y * inv;
        oz = 0.5f * cv.z + sv.z * inv;
        ow = 0.5f * cv.w + sv.w * inv;
    } else {
        ox = cv.x; oy = cv.y; oz = cv.z; ow = cv.w;
    }
    // out offset by 1 (loss at out[0]) -> scalar stores (4B aligned)
    float* o = out + 1 + (size_t)i * 4;
    o[0] = ox; o[1] = oy; o[2] = oz; o[3] = ow;

    // restore own scratch element to zero
    *sp = make_float4(0.0f, 0.0f, 0.0f, 0.0f);

    // ---- block-reduce loss partial -> one atomic per block ----
    #pragma unroll
    for (int off = 16; off > 0; off >>= 1)
        lp += __shfl_xor_sync(0xffffffffu, lp, off);

    __shared__ float warp_sums[8];
    if (lane == 0) warp_sums[wid] = lp;
    __syncthreads();
    if (threadIdx.x == 0) {
        float bs = 0.0f;
        #pragma unroll
        for (int w = 0; w < 8; w++) bs += warp_sums[w];
        atomicAdd(&g_loss, bs);
    }
}

// Tail: write loss scalar, reset g_loss and g_counts for the next call.
__global__ void __launch_bounds__(1024) tail_kernel(float* __restrict__ out)
{
    const int t = threadIdx.x;
    if (t < NUM_CLASSES) g_counts[t] = 0.0f;
    if (t == 0) {
        out[0] = 0.5f * g_loss / (float)BATCH;
        g_loss = 0.0f;
    }
}

extern "C" void kernel_launch(void* const* d_in, const int* in_sizes, int n_in,
                              void* d_out, int out_size)
{
    const float* features = (const float*)d_in[0];
    const int*   labels   = (const int*)d_in[1];
    const float* centers  = (const float*)d_in[2];
    float*       out      = (float*)d_out;

    (void)in_sizes; (void)n_in; (void)out_size;

    // 1) fused pass: sum(f^2) + scatter sums/counts  (one warp per 2 rows)
    center_main_kernel<<<BATCH / 16, 256>>>(features, labels);
    // 2) finalize: center update + loss assembly + sums re-zero
    finalize_kernel<<<(NUM_CLASSES * FEAT_DIM / 4) / 256, 256>>>(centers, out);
    // 3) tail: loss scalar + counts/loss reset
    tail_kernel<<<1, 1024>>>(out);
}